// round 11
// baseline (speedup 1.0000x reference)
#include <cuda_runtime.h>
#include <cuda_bf16.h>
#include <cuda_fp16.h>
#include <math.h>
#include <stdint.h>

#define HIDDEN 1024
#define NH 16
#define NKV 4
#define HD 64
#define SEQL 2048
#define BSZ 2
#define KVD (NKV*HD)            /* 256  */
#define QKVN (HIDDEN + 2*KVD)   /* 1536 */
#define MTOT (BSZ*SEQL)         /* 4096 */
#define WIN 1534
#define LOG2E 1.44269504088896340736f

#define WQ_OFF 0
#define WK_OFF (1024*1024)
#define WV_OFF (1280*1024)
#define WO_OFF (1536*1024)
#define WTOT   (2560*1024)

__device__ __align__(16) float   g_qkv[(size_t)MTOT * QKVN];
__device__ __align__(16) __half  g_ha[(size_t)MTOT * HIDDEN];
__device__ __align__(16) __half  g_w16h[(size_t)WTOT];
__device__ __align__(16) __half  g_w16l[(size_t)WTOT];
__device__ __align__(16) float   g_bias[QKVN];
__device__ __align__(16) __half  g_qh[(size_t)MTOT * HIDDEN];
__device__ __align__(16) __half  g_kh[(size_t)MTOT * KVD];
__device__ __align__(16) __half  g_vh[(size_t)MTOT * KVD];
__device__ __align__(16) __half  g_o16[(size_t)MTOT * HIDDEN];
__device__ __align__(16) float   g_am[BSZ * SEQL];
__device__ __align__(16) float2  g_sc[SEQL * 32];

// --------------------------- ptx helpers ----------------------------------
__device__ __forceinline__ void mma_f16(float* c, const unsigned* a, const unsigned* b) {
    asm volatile(
        "mma.sync.aligned.m16n8k16.row.col.f32.f16.f16.f32 "
        "{%0,%1,%2,%3}, {%4,%5,%6,%7}, {%8,%9}, {%0,%1,%2,%3};"
        : "+f"(c[0]), "+f"(c[1]), "+f"(c[2]), "+f"(c[3])
        : "r"(a[0]), "r"(a[1]), "r"(a[2]), "r"(a[3]), "r"(b[0]), "r"(b[1]));
}
#define LDSM_X4(R, ADDR) \
    asm volatile("ldmatrix.sync.aligned.m8n8.x4.shared.b16 {%0,%1,%2,%3}, [%4];" \
        : "=r"((R)[0]), "=r"((R)[1]), "=r"((R)[2]), "=r"((R)[3]) : "r"(ADDR))
#define LDSM_X4_T(R, ADDR) \
    asm volatile("ldmatrix.sync.aligned.m8n8.x4.trans.shared.b16 {%0,%1,%2,%3}, [%4];" \
        : "=r"((R)[0]), "=r"((R)[1]), "=r"((R)[2]), "=r"((R)[3]) : "r"(ADDR))
__device__ __forceinline__ void cp16(unsigned dst, const void* src) {
    asm volatile("cp.async.cg.shared.global [%0], [%1], 16;" :: "r"(dst), "l"(src) : "memory");
}
__device__ __forceinline__ void cp_commit() { asm volatile("cp.async.commit_group;" ::: "memory"); }
template<int N> __device__ __forceinline__ void cp_wait() {
    asm volatile("cp.async.wait_group %0;" :: "n"(N) : "memory");
}
__device__ __forceinline__ float fexp2(float x) {
    float y; asm("ex2.approx.f32 %0, %1;" : "=f"(y) : "f"(x)); return y;
}
__device__ __forceinline__ void split1h(float x, __half& h, __half& l) {
    h = __float2half_rn(x);
    l = __float2half_rn(x - __half2float(h));
}
__device__ __forceinline__ unsigned pack_h2(float x, float y) {
    __half2 h = __floats2half2_rn(x, y);
    return *reinterpret_cast<unsigned*>(&h);
}
__device__ __forceinline__ void split_pack2h(float x, float y, unsigned& hi, unsigned& lo) {
    __half hx, lx, hy, ly;
    split1h(x, hx, lx); split1h(y, hy, ly);
    __half2 hh = __halves2half2(hx, hy);
    __half2 ll = __halves2half2(lx, ly);
    hi = *reinterpret_cast<unsigned*>(&hh);
    lo = *reinterpret_cast<unsigned*>(&ll);
}

#define SCL (0.125f * LOG2E)
#define AMS (-10000.0f * LOG2E)

// ----------------- split all inputs + sincos + bias + amask (one launch) --
#define SPL_HS (MTOT*HIDDEN/4)
#define SPL_WQ (SPL_HS + HIDDEN*HIDDEN/4)
#define SPL_WK (SPL_WQ + KVD*HIDDEN/4)
#define SPL_WV (SPL_WK + KVD*HIDDEN/4)
#define SPL_WO (SPL_WV + HIDDEN*HIDDEN/4)
#define SPL_SC (SPL_WO + SEQL*32)
#define SPL_BI (SPL_SC + QKVN)
#define SPL_AM (SPL_BI + BSZ*SEQL)
__global__ void split_all_kernel(const float* __restrict__ hs,
                                 const float* __restrict__ Wq,
                                 const float* __restrict__ Wk,
                                 const float* __restrict__ Wv,
                                 const float* __restrict__ Wo,
                                 const float* __restrict__ bq,
                                 const float* __restrict__ bk,
                                 const float* __restrict__ bv,
                                 const float* __restrict__ amask) {
    int i = blockIdx.x * blockDim.x + threadIdx.x;
    if (i < SPL_HS) {
        float4 v = ((const float4*)hs)[i];
        uint2 p;
        p.x = pack_h2(v.x, v.y);
        p.y = pack_h2(v.z, v.w);
        ((uint2*)g_ha)[i] = p;
        return;
    }
    if (i < SPL_WO) {
        const float* src; int off;
        __half *dh, *dl;
        if (i < SPL_WQ)      { src = Wq; dh = g_w16h + WQ_OFF; dl = g_w16l + WQ_OFF; off = i - SPL_HS; }
        else if (i < SPL_WK) { src = Wk; dh = g_w16h + WK_OFF; dl = g_w16l + WK_OFF; off = i - SPL_WQ; }
        else if (i < SPL_WV) { src = Wv; dh = g_w16h + WV_OFF; dl = g_w16l + WV_OFF; off = i - SPL_WK; }
        else                 { src = Wo; dh = g_w16h + WO_OFF; dl = g_w16l + WO_OFF; off = i - SPL_WV; }
        float4 v = ((const float4*)src)[off];
        uint2 h, l;
        split_pack2h(v.x, v.y, h.x, l.x);
        split_pack2h(v.z, v.w, h.y, l.y);
        ((uint2*)dh)[off] = h;
        ((uint2*)dl)[off] = l;
        return;
    }
    if (i < SPL_SC) {
        int idx = i - SPL_WO;
        int s = idx >> 5, j = idx & 31;
        double invf = exp(-(double)j * 0.28782313662425572);
        double ang  = (double)s * invf;
        g_sc[idx] = make_float2((float)sin(ang), (float)cos(ang));
        return;
    }
    if (i < SPL_BI) {
        int idx = i - SPL_SC;
        g_bias[idx] = (idx < HIDDEN) ? bq[idx]
                     : (idx < HIDDEN + KVD ? bk[idx - HIDDEN] : bv[idx - HIDDEN - KVD]);
        return;
    }
    if (i < SPL_AM) {
        int idx = i - SPL_BI;
        g_am[idx] = amask[idx] * AMS;
    }
}

// rope on q,k; outputs fp16 single: q, k, v
#define NQ_T (MTOT*NH*32)
#define NK_T (MTOT*NKV*32)
#define NV_T (MTOT*64)
__global__ void rope_split_kernel() {
    int idx = blockIdx.x * blockDim.x + threadIdx.x;
    if (idx < NQ_T) {
        int j = idx & 31, r = idx >> 5;
        int h = r % NH, m = r / NH;
        float2 sc = g_sc[((m & (SEQL - 1)) << 5) | j];
        const float* base = g_qkv + (size_t)m * QKVN + h * HD;
        float xr = base[j], xp = base[j + 32];
        float a = xr * sc.y - xp * sc.x;
        float b = xr * sc.x + xp * sc.y;
        size_t o = (size_t)m * HIDDEN + h * HD + j;
        g_qh[o]      = __float2half_rn(a);
        g_qh[o + 32] = __float2half_rn(b);
        return;
    }
    idx -= NQ_T;
    if (idx < NK_T) {
        int j = idx & 31, r = idx >> 5;
        int h = r % NKV, m = r / NKV;
        float2 sc = g_sc[((m & (SEQL - 1)) << 5) | j];
        const float* base = g_qkv + (size_t)m * QKVN + HIDDEN + h * HD;
        float xr = base[j], xp = base[j + 32];
        float a = xr * sc.y - xp * sc.x;
        float b = xr * sc.x + xp * sc.y;
        size_t o = (size_t)m * KVD + h * HD + j;
        g_kh[o]      = __float2half_rn(a);
        g_kh[o + 32] = __float2half_rn(b);
        return;
    }
    idx -= NK_T;
    if (idx < NV_T) {
        int c4 = (idx & 63) * 4, m = idx >> 6;
        float4 v = *(const float4*)(g_qkv + (size_t)m * QKVN + HIDDEN + KVD + c4);
        uint2 p;
        p.x = pack_h2(v.x, v.y);
        p.y = pack_h2(v.z, v.w);
        *(uint2*)(g_vh + (size_t)m * KVD + c4) = p;
    }
}

// ---------------------------------------------------------------------------
// fp16 2-term GEMM: A single fp16, B hi/lo fp16. BM=BN=128, BK=64, 8 warps,
// 2 stages. Same k-order as BK=32 version (numerically identical).
// ---------------------------------------------------------------------------
#define GP 72
#define G_STG (3*128*GP)
#define GEMM_SMEM (2*G_STG*2)      /* 110592 B */

__global__ __launch_bounds__(256) void hgemm_kernel(
    const __half* __restrict__ A,
    const __half* __restrict__ Bh, const __half* __restrict__ Bl,
    const float* __restrict__ bias, float* __restrict__ C, int N)
{
    extern __shared__ __align__(16) __half smg[];
    const unsigned sb = (unsigned)__cvta_generic_to_shared(smg);
    const int K = HIDDEN;
    const int bm = blockIdx.y * 128;
    const int bn = blockIdx.x * 128;
    const int tid = threadIdx.x, wid = tid >> 5, lane = tid & 31;
    const int g = lane >> 2, t = lane & 3;
    const int ln7 = lane & 7, sel = lane >> 3;
    const int wm = (wid >> 2) * 64, wn = (wid & 3) * 32;
    const int loffA = (((sel & 1) * 8 + ln7) * GP + (sel >> 1) * 8) * 2;
    const int loffB = (((sel >> 1) * 8 + ln7) * GP + (sel & 1) * 8) * 2;

    const __half* srcs[3] = {A + (size_t)bm * K, Bh + (size_t)bn * K, Bl + (size_t)bn * K};

    float acc[4][4][4];
    #pragma unroll
    for (int i = 0; i < 4; i++)
        #pragma unroll
        for (int j = 0; j < 4; j++)
            #pragma unroll
            for (int c = 0; c < 4; c++) acc[i][j][c] = 0.f;

    // 3 arrays x 128 rows x 8 chunks(16B) = 3072 chunks, 12 per thread
    auto issue = [&](int k0, int stg) {
        #pragma unroll
        for (int l = 0; l < 12; l++) {
            int idx = tid + l * 256;
            int arr = idx >> 10;
            int rem = idx & 1023;
            int row = rem >> 3, ch = rem & 7;
            const __half* s = srcs[arr] + (size_t)row * K + k0 + ch * 8;
            unsigned d = sb + (stg * G_STG + arr * 128 * GP + row * GP + ch * 8) * 2;
            cp16(d, s);
        }
    };

    issue(0, 0); cp_commit();
    const int NTK = K / 64;                 /* 16 */
    for (int kt = 0; kt < NTK; kt++) {
        if (kt + 1 < NTK) issue((kt + 1) * 64, (kt + 1) & 1);
        cp_commit();
        cp_wait<1>();
        __syncthreads();
        const unsigned base = sb + ((kt & 1) * G_STG) * 2;
        #pragma unroll
        for (int ks = 0; ks < 64; ks += 16) {
            unsigned a4[4][4];
            #pragma unroll
            for (int mt = 0; mt < 4; mt++)
                LDSM_X4(a4[mt], base + ((wm + mt * 16) * GP + ks) * 2 + loffA);
            #pragma unroll
            for (int ntp = 0; ntp < 2; ntp++) {
                unsigned bh4[4], bl4[4];
                LDSM_X4(bh4, base + (128 * GP + (wn + ntp * 16) * GP + ks) * 2 + loffB);
                LDSM_X4(bl4, base + (2 * 128 * GP + (wn + ntp * 16) * GP + ks) * 2 + loffB);
                #pragma unroll
                for (int mt = 0; mt < 4; mt++) {
                    mma_f16(acc[mt][2 * ntp], a4[mt], &bh4[0]);
                    mma_f16(acc[mt][2 * ntp], a4[mt], &bl4[0]);
                    mma_f16(acc[mt][2 * ntp + 1], a4[mt], &bh4[2]);
                    mma_f16(acc[mt][2 * ntp + 1], a4[mt], &bl4[2]);
                }
            }
        }
        __syncthreads();
    }

    #pragma unroll
    for (int mt = 0; mt < 4; mt++)
        #pragma unroll
        for (int nt = 0; nt < 4; nt++) {
            int r = bm + wm + mt * 16 + g;
            int ccol = wn + nt * 8 + 2 * t;
            float b0v = 0.f, b1v = 0.f;
            if (bias) { b0v = bias[bn + ccol]; b1v = bias[bn + ccol + 1]; }
            *(float2*)(C + (size_t)r * N + bn + ccol) =
                make_float2(acc[mt][nt][0] + b0v, acc[mt][nt][1] + b1v);
            *(float2*)(C + (size_t)(r + 8) * N + bn + ccol) =
                make_float2(acc[mt][nt][2] + b0v, acc[mt][nt][3] + b1v);
        }
}

// ---------------------------------------------------------------------------
// Flash attention v8 (single fp16 K/V, Bc=128): Br=64, 4 warps,
// 2 smem arrays/stage (128 keys each), 2-stage cp.async.
// ---------------------------------------------------------------------------
#define AP 72
#define A_ARR (128*AP)
#define A_STG (2*A_ARR)
#define ATTN_SMEM (2*A_STG*2)      /* 73728 B */

__global__ __launch_bounds__(128) void attn_kernel()
{
    extern __shared__ __align__(16) __half sma[];
    const unsigned sb = (unsigned)__cvta_generic_to_shared(sma);

    const int qt0 = blockIdx.x * 64;
    const int b   = blockIdx.y >> 4;
    const int h   = blockIdx.y & 15;
    const int kvh = h >> 2;
    const int tid = threadIdx.x, wid = tid >> 5, lane = tid & 31;
    const int g = lane >> 2, t = lane & 3;
    const int ln7 = lane & 7, sel = lane >> 3;
    const int loffK = (((sel >> 1) * 8 + ln7) * AP + (sel & 1) * 8) * 2;
    const int loffV = (((sel & 1) * 8 + ln7) * AP + (sel >> 1) * 8) * 2;
    const int rq0 = qt0 + wid * 16 + g;

    unsigned Qah[4][4];
    {
        const size_t rb = (size_t)(b * SEQL + rq0) * HIDDEN + h * HD + 2 * t;
        #pragma unroll
        for (int ks = 0; ks < 4; ks++) {
            int d = ks * 16;
            Qah[ks][0] = *(const unsigned*)(g_qh + rb + d);
            Qah[ks][1] = *(const unsigned*)(g_qh + rb + 8 * HIDDEN + d);
            Qah[ks][2] = *(const unsigned*)(g_qh + rb + d + 8);
            Qah[ks][3] = *(const unsigned*)(g_qh + rb + 8 * HIDDEN + d + 8);
        }
    }

    const size_t kvbase = (size_t)(b * SEQL) * KVD + kvh * HD;
    const __half* srcs[2] = {g_kh + kvbase, g_vh + kvbase};

    // 2 arrays x 128 rows x 8 chunks = 2048 chunks, 16 per thread
    auto issue = [&](int kt0, int stg) {
        #pragma unroll
        for (int l = 0; l < 16; l++) {
            int idx = tid + l * 128;
            int arr = idx >> 10;
            int rem = idx & 1023;
            int row = rem >> 3, ch = rem & 7;
            const __half* s = srcs[arr] + (size_t)(kt0 + row) * KVD + ch * 8;
            unsigned d = sb + (stg * A_STG + arr * A_ARR + row * AP + ch * 8) * 2;
            cp16(d, s);
        }
    };

    float o[8][4];
    #pragma unroll
    for (int dt = 0; dt < 8; dt++)
        #pragma unroll
        for (int c = 0; c < 4; c++) o[dt][c] = 0.f;
    float m0 = -1e30f, m1 = -1e30f, l0 = 0.f, l1 = 0.f;

    const int ktmax = min(SEQL, qt0 + 63 + WIN + 1);
    const int NT = (ktmax + 127) >> 7;

    issue(0, 0); cp_commit();
    for (int ti = 0; ti < NT; ti++) {
        const int kt0 = ti * 128;
        if (ti + 1 < NT) issue((ti + 1) * 128, (ti + 1) & 1);
        cp_commit();
        cp_wait<1>();
        __syncthreads();
        const unsigned base = sb + ((ti & 1) * A_STG) * 2;
        const unsigned KH = base, VH = base + A_ARR * 2;

        // ---- S = Q K^T ----
        float s[16][4];
        #pragma unroll
        for (int nt = 0; nt < 16; nt++)
            #pragma unroll
            for (int c = 0; c < 4; c++) s[nt][c] = 0.f;

        #pragma unroll
        for (int ks = 0; ks < 4; ks++) {
            #pragma unroll
            for (int ntp = 0; ntp < 8; ntp++) {
                unsigned kh[4];
                LDSM_X4(kh, KH + (ntp * 16 * AP + ks * 16) * 2 + loffK);
                mma_f16(s[2 * ntp], Qah[ks], &kh[0]);
                mma_f16(s[2 * ntp + 1], Qah[ks], &kh[2]);
            }
        }

        // ---- scale + masks ----
        if (kt0 + 127 - qt0 - wid * 16 <= WIN) {
            #pragma unroll
            for (int nt = 0; nt < 16; nt++) {
                int col0 = kt0 + nt * 8 + 2 * t;
                float2 amv = *(const float2*)(g_am + (size_t)b * SEQL + col0);
                s[nt][0] = fmaf(s[nt][0], SCL, amv.x);
                s[nt][1] = fmaf(s[nt][1], SCL, amv.y);
                s[nt][2] = fmaf(s[nt][2], SCL, amv.x);
                s[nt][3] = fmaf(s[nt][3], SCL, amv.y);
            }
        } else {
            #pragma unroll
            for (int nt = 0; nt < 16; nt++) {
                int col0 = kt0 + nt * 8 + 2 * t;
                float2 amv = *(const float2*)(g_am + (size_t)b * SEQL + col0);
                s[nt][0] = (col0     - rq0     > WIN) ? -1e30f : fmaf(s[nt][0], SCL, amv.x);
                s[nt][1] = (col0 + 1 - rq0     > WIN) ? -1e30f : fmaf(s[nt][1], SCL, amv.y);
                s[nt][2] = (col0     - rq0 - 8 > WIN) ? -1e30f : fmaf(s[nt][2], SCL, amv.x);
                s[nt][3] = (col0 + 1 - rq0 - 8 > WIN) ? -1e30f : fmaf(s[nt][3], SCL, amv.y);
            }
        }

        // ---- online softmax ----
        float mx0 = -1e30f, mx1 = -1e30f;
        #pragma unroll
        for (int nt = 0; nt < 16; nt++) {
            mx0 = fmaxf(mx0, fmaxf(s[nt][0], s[nt][1]));
            mx1 = fmaxf(mx1, fmaxf(s[nt][2], s[nt][3]));
        }
        mx0 = fmaxf(mx0, __shfl_xor_sync(0xffffffffu, mx0, 1));
        mx0 = fmaxf(mx0, __shfl_xor_sync(0xffffffffu, mx0, 2));
        mx1 = fmaxf(mx1, __shfl_xor_sync(0xffffffffu, mx1, 1));
        mx1 = fmaxf(mx1, __shfl_xor_sync(0xffffffffu, mx1, 2));
        float mn0 = fmaxf(m0, mx0), mn1 = fmaxf(m1, mx1);
        float alpha0 = fexp2(m0 - mn0), alpha1 = fexp2(m1 - mn1);
        m0 = mn0; m1 = mn1;
        float ls0 = 0.f, ls1 = 0.f;
        #pragma unroll
        for (int nt = 0; nt < 16; nt++) {
            s[nt][0] = fexp2(s[nt][0] - mn0);
            s[nt][1] = fexp2(s[nt][1] - mn0);
            s[nt][2] = fexp2(s[nt][2] - mn1);
            s[nt][3] = fexp2(s[nt][3] - mn1);
            ls0 += s[nt][0] + s[nt][1];
            ls1 += s[nt][2] + s[nt][3];
        }
        ls0 += __shfl_xor_sync(0xffffffffu, ls0, 1);
        ls0 += __shfl_xor_sync(0xffffffffu, ls0, 2);
        ls1 += __shfl_xor_sync(0xffffffffu, ls1, 1);
        ls1 += __shfl_xor_sync(0xffffffffu, ls1, 2);
        l0 = l0 * alpha0 + ls0;
        l1 = l1 * alpha1 + ls1;
        #pragma unroll
        for (int dt = 0; dt < 8; dt++) {
            o[dt][0] *= alpha0; o[dt][1] *= alpha0;
            o[dt][2] *= alpha1; o[dt][3] *= alpha1;
        }

        // ---- O += P16 x V ----
        #pragma unroll
        for (int kp = 0; kp < 8; kp++) {
            unsigned pah[4];
            pah[0] = pack_h2(s[2 * kp][0],     s[2 * kp][1]);
            pah[1] = pack_h2(s[2 * kp][2],     s[2 * kp][3]);
            pah[2] = pack_h2(s[2 * kp + 1][0], s[2 * kp + 1][1]);
            pah[3] = pack_h2(s[2 * kp + 1][2], s[2 * kp + 1][3]);
            #pragma unroll
            for (int dtp = 0; dtp < 4; dtp++) {
                unsigned vh[4];
                LDSM_X4_T(vh, VH + (kp * 16 * AP + dtp * 16) * 2 + loffV);
                mma_f16(o[2 * dtp], pah, &vh[0]);
                mma_f16(o[2 * dtp + 1], pah, &vh[2]);
            }
        }
        __syncthreads();
    }

    float inv0 = 1.f / l0, inv1 = 1.f / l1;
    const size_t ob = (size_t)(b * SEQL + rq0) * HIDDEN + h * HD + 2 * t;
    #pragma unroll
    for (int dt = 0; dt < 8; dt++) {
        int dc = dt * 8;
        *(unsigned*)(g_o16 + ob + dc) = pack_h2(o[dt][0] * inv0, o[dt][1] * inv0);
        *(unsigned*)(g_o16 + ob + 8 * HIDDEN + dc) = pack_h2(o[dt][2] * inv1, o[dt][3] * inv1);
    }
}

extern "C" void kernel_launch(void* const* d_in, const int* in_sizes, int n_in,
                              void* d_out, int out_size) {
    const float* hs = (const float*)d_in[0];
    const float* am = (const float*)d_in[1];
    const float* Wq = (const float*)d_in[2];
    const float* bq = (const float*)d_in[3];
    const float* Wk = (const float*)d_in[4];
    const float* bk = (const float*)d_in[5];
    const float* Wv = (const float*)d_in[6];
    const float* bv = (const float*)d_in[7];
    const float* Wo = (const float*)d_in[8];
    float* out = (float*)d_out;

    float *qkv, *biasp;
    __half *ha, *wh, *wl, *o16;
    cudaGetSymbolAddress((void**)&qkv,   g_qkv);
    cudaGetSymbolAddress((void**)&biasp, g_bias);
    cudaGetSymbolAddress((void**)&ha,  g_ha);
    cudaGetSymbolAddress((void**)&wh,  g_w16h);
    cudaGetSymbolAddress((void**)&wl,  g_w16l);
    cudaGetSymbolAddress((void**)&o16, g_o16);

    cudaFuncSetAttribute(hgemm_kernel, cudaFuncAttributeMaxDynamicSharedMemorySize, GEMM_SMEM);
    cudaFuncSetAttribute(attn_kernel, cudaFuncAttributeMaxDynamicSharedMemorySize, ATTN_SMEM);

    split_all_kernel<<<(SPL_AM + 255) / 256, 256>>>(hs, Wq, Wk, Wv, Wo, bq, bk, bv, am);

    hgemm_kernel<<<dim3(QKVN / 128, MTOT / 128), 256, GEMM_SMEM>>>(
        ha, wh, wl, biasp, qkv, QKVN);

    rope_split_kernel<<<(NQ_T + NK_T + NV_T + 255) / 256, 256>>>();

    attn_kernel<<<dim3(SEQL / 64, BSZ * NH), 128, ATTN_SMEM>>>();

    hgemm_kernel<<<dim3(HIDDEN / 128, MTOT / 128), 256, GEMM_SMEM>>>(
        o16, wh + WO_OFF, wl + WO_OFF, nullptr, out, HIDDEN);
}

// round 14
// speedup vs baseline: 1.0145x; 1.0145x over previous
#include <cuda_runtime.h>
#include <cuda_bf16.h>
#include <cuda_fp16.h>
#include <math.h>
#include <stdint.h>

#define HIDDEN 1024
#define NH 16
#define NKV 4
#define HD 64
#define SEQL 2048
#define BSZ 2
#define KVD (NKV*HD)            /* 256  */
#define QKVN (HIDDEN + 2*KVD)   /* 1536 */
#define MTOT (BSZ*SEQL)         /* 4096 */
#define WIN 1534
#define LOG2E 1.44269504088896340736f

#define WQ_OFF 0
#define WK_OFF (1024*1024)
#define WV_OFF (1280*1024)
#define WO_OFF (1536*1024)
#define WTOT   (2560*1024)

__device__ __align__(16) __half  g_ha[(size_t)MTOT * HIDDEN];
__device__ __align__(16) __half  g_w16h[(size_t)WTOT];
__device__ __align__(16) __half  g_w16l[(size_t)WTOT];
__device__ __align__(16) float   g_bias[QKVN];
__device__ __align__(16) __half  g_qh[(size_t)MTOT * HIDDEN];
__device__ __align__(16) __half  g_kh[(size_t)MTOT * KVD];
__device__ __align__(16) __half  g_vh[(size_t)MTOT * KVD];
__device__ __align__(16) __half  g_o16[(size_t)MTOT * HIDDEN];
__device__ __align__(16) float   g_am[BSZ * SEQL];
__device__ __align__(16) float2  g_sc[SEQL * 32];

// --------------------------- ptx helpers ----------------------------------
__device__ __forceinline__ void mma_f16(float* c, const unsigned* a, const unsigned* b) {
    asm volatile(
        "mma.sync.aligned.m16n8k16.row.col.f32.f16.f16.f32 "
        "{%0,%1,%2,%3}, {%4,%5,%6,%7}, {%8,%9}, {%0,%1,%2,%3};"
        : "+f"(c[0]), "+f"(c[1]), "+f"(c[2]), "+f"(c[3])
        : "r"(a[0]), "r"(a[1]), "r"(a[2]), "r"(a[3]), "r"(b[0]), "r"(b[1]));
}
#define LDSM_X4(R, ADDR) \
    asm volatile("ldmatrix.sync.aligned.m8n8.x4.shared.b16 {%0,%1,%2,%3}, [%4];" \
        : "=r"((R)[0]), "=r"((R)[1]), "=r"((R)[2]), "=r"((R)[3]) : "r"(ADDR))
#define LDSM_X4_T(R, ADDR) \
    asm volatile("ldmatrix.sync.aligned.m8n8.x4.trans.shared.b16 {%0,%1,%2,%3}, [%4];" \
        : "=r"((R)[0]), "=r"((R)[1]), "=r"((R)[2]), "=r"((R)[3]) : "r"(ADDR))
__device__ __forceinline__ void cp16(unsigned dst, const void* src) {
    asm volatile("cp.async.cg.shared.global [%0], [%1], 16;" :: "r"(dst), "l"(src) : "memory");
}
__device__ __forceinline__ void cp_commit() { asm volatile("cp.async.commit_group;" ::: "memory"); }
template<int N> __device__ __forceinline__ void cp_wait() {
    asm volatile("cp.async.wait_group %0;" :: "n"(N) : "memory");
}
__device__ __forceinline__ float fexp2(float x) {
    float y; asm("ex2.approx.f32 %0, %1;" : "=f"(y) : "f"(x)); return y;
}
__device__ __forceinline__ void split1h(float x, __half& h, __half& l) {
    h = __float2half_rn(x);
    l = __float2half_rn(x - __half2float(h));
}
__device__ __forceinline__ unsigned pack_h2(float x, float y) {
    __half2 h = __floats2half2_rn(x, y);
    return *reinterpret_cast<unsigned*>(&h);
}
__device__ __forceinline__ void split_pack2h(float x, float y, unsigned& hi, unsigned& lo) {
    __half hx, lx, hy, ly;
    split1h(x, hx, lx); split1h(y, hy, ly);
    __half2 hh = __halves2half2(hx, hy);
    __half2 ll = __halves2half2(lx, ly);
    hi = *reinterpret_cast<unsigned*>(&hh);
    lo = *reinterpret_cast<unsigned*>(&ll);
}

#define SCL (0.125f * LOG2E)
#define AMS (-10000.0f * LOG2E)

// ----------------- split all inputs + sincos + bias + amask (one launch) --
#define SPL_HS (MTOT*HIDDEN/4)
#define SPL_WQ (SPL_HS + HIDDEN*HIDDEN/4)
#define SPL_WK (SPL_WQ + KVD*HIDDEN/4)
#define SPL_WV (SPL_WK + KVD*HIDDEN/4)
#define SPL_WO (SPL_WV + HIDDEN*HIDDEN/4)
#define SPL_SC (SPL_WO + SEQL*32)
#define SPL_BI (SPL_SC + QKVN)
#define SPL_AM (SPL_BI + BSZ*SEQL)
__global__ void split_all_kernel(const float* __restrict__ hs,
                                 const float* __restrict__ Wq,
                                 const float* __restrict__ Wk,
                                 const float* __restrict__ Wv,
                                 const float* __restrict__ Wo,
                                 const float* __restrict__ bq,
                                 const float* __restrict__ bk,
                                 const float* __restrict__ bv,
                                 const float* __restrict__ amask) {
    int i = blockIdx.x * blockDim.x + threadIdx.x;
    if (i < SPL_HS) {
        float4 v = ((const float4*)hs)[i];
        uint2 p;
        p.x = pack_h2(v.x, v.y);
        p.y = pack_h2(v.z, v.w);
        ((uint2*)g_ha)[i] = p;
        return;
    }
    if (i < SPL_WO) {
        const float* src; int off;
        __half *dh, *dl;
        if (i < SPL_WQ)      { src = Wq; dh = g_w16h + WQ_OFF; dl = g_w16l + WQ_OFF; off = i - SPL_HS; }
        else if (i < SPL_WK) { src = Wk; dh = g_w16h + WK_OFF; dl = g_w16l + WK_OFF; off = i - SPL_WQ; }
        else if (i < SPL_WV) { src = Wv; dh = g_w16h + WV_OFF; dl = g_w16l + WV_OFF; off = i - SPL_WK; }
        else                 { src = Wo; dh = g_w16h + WO_OFF; dl = g_w16l + WO_OFF; off = i - SPL_WV; }
        float4 v = ((const float4*)src)[off];
        uint2 h, l;
        split_pack2h(v.x, v.y, h.x, l.x);
        split_pack2h(v.z, v.w, h.y, l.y);
        ((uint2*)dh)[off] = h;
        ((uint2*)dl)[off] = l;
        return;
    }
    if (i < SPL_SC) {
        int idx = i - SPL_WO;
        int s = idx >> 5, j = idx & 31;
        double invf = exp(-(double)j * 0.28782313662425572);
        double ang  = (double)s * invf;
        g_sc[idx] = make_float2((float)sin(ang), (float)cos(ang));
        return;
    }
    if (i < SPL_BI) {
        int idx = i - SPL_SC;
        g_bias[idx] = (idx < HIDDEN) ? bq[idx]
                     : (idx < HIDDEN + KVD ? bk[idx - HIDDEN] : bv[idx - HIDDEN - KVD]);
        return;
    }
    if (i < SPL_AM) {
        int idx = i - SPL_BI;
        g_am[idx] = amask[idx] * AMS;
    }
}

// ---------------------------------------------------------------------------
// fp16 2-term GEMM: A single fp16, B hi/lo fp16. BM=BN=128, BK=32, 8 warps,
// 2 stages (R10-proven mainloop).
// MODE 0: C fp32 (+bias)              [O-proj]
// MODE 1: fused epilogue — bias + rope(Q,K)/convert(V) -> fp16 globals.
// ---------------------------------------------------------------------------
#define GP 40
#define G_STG (3*128*GP)
#define EP 130                               /* fp32 staging row stride */
#define GEMM_SMEM (128*EP*4)                 /* 66560 > 2*G_STG*2=61440 */

template<int MODE>
__global__ __launch_bounds__(256) void hgemm_kernel(
    const __half* __restrict__ A,
    const __half* __restrict__ Bh, const __half* __restrict__ Bl,
    const float* __restrict__ bias, float* __restrict__ C, int N)
{
    extern __shared__ __align__(16) __half smg[];
    const unsigned sb = (unsigned)__cvta_generic_to_shared(smg);
    const int K = HIDDEN;
    const int bm = blockIdx.y * 128;
    const int bn = blockIdx.x * 128;
    const int tid = threadIdx.x, wid = tid >> 5, lane = tid & 31;
    const int g = lane >> 2, t = lane & 3;
    const int ln7 = lane & 7, sel = lane >> 3;
    const int wm = (wid >> 2) * 64, wn = (wid & 3) * 32;
    const int loffA = (((sel & 1) * 8 + ln7) * GP + (sel >> 1) * 8) * 2;
    const int loffB = (((sel >> 1) * 8 + ln7) * GP + (sel & 1) * 8) * 2;

    const __half* srcs[3] = {A + (size_t)bm * K, Bh + (size_t)bn * K, Bl + (size_t)bn * K};

    float acc[4][4][4];
    #pragma unroll
    for (int i = 0; i < 4; i++)
        #pragma unroll
        for (int j = 0; j < 4; j++)
            #pragma unroll
            for (int c = 0; c < 4; c++) acc[i][j][c] = 0.f;

    auto issue = [&](int k0, int stg) {
        #pragma unroll
        for (int l = 0; l < 6; l++) {
            int arr = l >> 1;
            int q = tid + (l & 1) * 256;
            int row = q >> 2, ch = q & 3;
            const __half* s = srcs[arr] + (size_t)row * K + k0 + ch * 8;
            unsigned d = sb + (stg * G_STG + arr * 128 * GP + row * GP + ch * 8) * 2;
            cp16(d, s);
        }
    };

    issue(0, 0); cp_commit();
    const int NTK = K / 32;
    for (int kt = 0; kt < NTK; kt++) {
        if (kt + 1 < NTK) issue((kt + 1) * 32, (kt + 1) & 1);
        cp_commit();
        cp_wait<1>();
        __syncthreads();
        const unsigned base = sb + ((kt & 1) * G_STG) * 2;
        #pragma unroll
        for (int ks = 0; ks < 32; ks += 16) {
            unsigned a4[4][4];
            #pragma unroll
            for (int mt = 0; mt < 4; mt++)
                LDSM_X4(a4[mt], base + ((wm + mt * 16) * GP + ks) * 2 + loffA);
            #pragma unroll
            for (int ntp = 0; ntp < 2; ntp++) {
                unsigned bh4[4], bl4[4];
                LDSM_X4(bh4, base + (128 * GP + (wn + ntp * 16) * GP + ks) * 2 + loffB);
                LDSM_X4(bl4, base + (2 * 128 * GP + (wn + ntp * 16) * GP + ks) * 2 + loffB);
                #pragma unroll
                for (int mt = 0; mt < 4; mt++) {
                    mma_f16(acc[mt][2 * ntp], a4[mt], &bh4[0]);
                    mma_f16(acc[mt][2 * ntp], a4[mt], &bl4[0]);
                    mma_f16(acc[mt][2 * ntp + 1], a4[mt], &bh4[2]);
                    mma_f16(acc[mt][2 * ntp + 1], a4[mt], &bl4[2]);
                }
            }
        }
        __syncthreads();
    }

    if (MODE == 0) {
        #pragma unroll
        for (int mt = 0; mt < 4; mt++)
            #pragma unroll
            for (int nt = 0; nt < 4; nt++) {
                int r = bm + wm + mt * 16 + g;
                int ccol = wn + nt * 8 + 2 * t;
                float b0v = 0.f, b1v = 0.f;
                if (bias) { b0v = bias[bn + ccol]; b1v = bias[bn + ccol + 1]; }
                *(float2*)(C + (size_t)r * N + bn + ccol) =
                    make_float2(acc[mt][nt][0] + b0v, acc[mt][nt][1] + b1v);
                *(float2*)(C + (size_t)(r + 8) * N + bn + ccol) =
                    make_float2(acc[mt][nt][2] + b0v, acc[mt][nt][3] + b1v);
            }
        return;
    }

    // ---- MODE 1: stage fp32 tile (+bias) in smem, then rope/convert ----
    float* st = (float*)smg;
    #pragma unroll
    for (int mt = 0; mt < 4; mt++)
        #pragma unroll
        for (int nt = 0; nt < 4; nt++) {
            int r = wm + mt * 16 + g;
            int ccol = wn + nt * 8 + 2 * t;
            float b0v = bias[bn + ccol], b1v = bias[bn + ccol + 1];
            *(float2*)&st[r * EP + ccol] =
                make_float2(acc[mt][nt][0] + b0v, acc[mt][nt][1] + b1v);
            *(float2*)&st[(r + 8) * EP + ccol] =
                make_float2(acc[mt][nt][2] + b0v, acc[mt][nt][3] + b1v);
        }
    __syncthreads();

    if (bn < HIDDEN + KVD) {
        // Q (bn<1024) or K (1024<=bn<1280): rope then fp16
        __half* dst   = (bn < HIDDEN) ? g_qh : g_kh;
        const int str = (bn < HIDDEN) ? HIDDEN : KVD;
        const int noff = (bn < HIDDEN) ? bn : bn - HIDDEN;
        #pragma unroll
        for (int l = 0; l < 32; l++) {
            int idx = tid + l * 256;
            int row = idx >> 6;            // 0..127
            int p   = idx & 63;            // pair id: head(1b) x j(5b)
            int head = p >> 5, j = p & 31;
            int cl = head * 64 + j;
            float xr = st[row * EP + cl];
            float xp = st[row * EP + cl + 32];
            int m = bm + row;
            float2 sc = g_sc[(((m & (SEQL - 1))) << 5) | j];
            size_t o = (size_t)m * str + noff + cl;
            dst[o]      = __float2half_rn(xr * sc.y - xp * sc.x);
            dst[o + 32] = __float2half_rn(xr * sc.x + xp * sc.y);
        }
    } else {
        // V: straight fp16 convert
        const int noff = bn - HIDDEN - KVD;
        #pragma unroll
        for (int l = 0; l < 32; l++) {
            int idx = tid + l * 256;
            int row = idx >> 6;
            int c2  = (idx & 63) * 2;
            float x = st[row * EP + c2];
            float y = st[row * EP + c2 + 1];
            int m = bm + row;
            *(unsigned*)(g_vh + (size_t)m * KVD + noff + c2) = pack_h2(x, y);
        }
    }
}

// ---------------------------------------------------------------------------
// Flash attention (R10-proven): single fp16 K/V, Br=Bc=64, 4 warps,
// 2 smem arrays/stage, 2-stage cp.async, exp2 softmax, fp16 P+output.
// ---------------------------------------------------------------------------
#define AP 72
#define A_ARR (64*AP)
#define A_STG (2*A_ARR)
#define ATTN_SMEM (2*A_STG*2)      /* 36864 B */

__global__ __launch_bounds__(128) void attn_kernel()
{
    extern __shared__ __align__(16) __half sma[];
    const unsigned sb = (unsigned)__cvta_generic_to_shared(sma);

    const int qt0 = blockIdx.x * 64;
    const int b   = blockIdx.y >> 4;
    const int h   = blockIdx.y & 15;
    const int kvh = h >> 2;
    const int tid = threadIdx.x, wid = tid >> 5, lane = tid & 31;
    const int g = lane >> 2, t = lane & 3;
    const int ln7 = lane & 7, sel = lane >> 3;
    const int loffK = (((sel >> 1) * 8 + ln7) * AP + (sel & 1) * 8) * 2;
    const int loffV = (((sel & 1) * 8 + ln7) * AP + (sel >> 1) * 8) * 2;
    const int rq0 = qt0 + wid * 16 + g;

    unsigned Qah[4][4];
    {
        const size_t rb = (size_t)(b * SEQL + rq0) * HIDDEN + h * HD + 2 * t;
        #pragma unroll
        for (int ks = 0; ks < 4; ks++) {
            int d = ks * 16;
            Qah[ks][0] = *(const unsigned*)(g_qh + rb + d);
            Qah[ks][1] = *(const unsigned*)(g_qh + rb + 8 * HIDDEN + d);
            Qah[ks][2] = *(const unsigned*)(g_qh + rb + d + 8);
            Qah[ks][3] = *(const unsigned*)(g_qh + rb + 8 * HIDDEN + d + 8);
        }
    }

    const size_t kvbase = (size_t)(b * SEQL) * KVD + kvh * HD;
    const __half* srcs[2] = {g_kh + kvbase, g_vh + kvbase};

    auto issue = [&](int kt0, int stg) {
        #pragma unroll
        for (int l = 0; l < 8; l++) {
            int arr = l >> 2;
            int q = tid + (l & 3) * 128;
            int row = q >> 3, ch = q & 7;
            const __half* s = srcs[arr] + (size_t)(kt0 + row) * KVD + ch * 8;
            unsigned d = sb + (stg * A_STG + arr * A_ARR + row * AP + ch * 8) * 2;
            cp16(d, s);
        }
    };

    float o[8][4];
    #pragma unroll
    for (int dt = 0; dt < 8; dt++)
        #pragma unroll
        for (int c = 0; c < 4; c++) o[dt][c] = 0.f;
    float m0 = -1e30f, m1 = -1e30f, l0 = 0.f, l1 = 0.f;

    const int ktmax = min(SEQL, qt0 + 63 + WIN + 1);
    const int NT = (ktmax + 63) >> 6;

    issue(0, 0); cp_commit();
    for (int ti = 0; ti < NT; ti++) {
        const int kt0 = ti * 64;
        if (ti + 1 < NT) issue((ti + 1) * 64, (ti + 1) & 1);
        cp_commit();
        cp_wait<1>();
        __syncthreads();
        const unsigned base = sb + ((ti & 1) * A_STG) * 2;
        const unsigned KH = base, VH = base + A_ARR * 2;

        float s[8][4];
        #pragma unroll
        for (int nt = 0; nt < 8; nt++)
            #pragma unroll
            for (int c = 0; c < 4; c++) s[nt][c] = 0.f;

        #pragma unroll
        for (int ks = 0; ks < 4; ks++) {
            #pragma unroll
            for (int ntp = 0; ntp < 4; ntp++) {
                unsigned kh[4];
                LDSM_X4(kh, KH + (ntp * 16 * AP + ks * 16) * 2 + loffK);
                mma_f16(s[2 * ntp], Qah[ks], &kh[0]);
                mma_f16(s[2 * ntp + 1], Qah[ks], &kh[2]);
            }
        }

        if (kt0 + 63 - qt0 - wid * 16 <= WIN) {
            #pragma unroll
            for (int nt = 0; nt < 8; nt++) {
                int col0 = kt0 + nt * 8 + 2 * t;
                float2 amv = *(const float2*)(g_am + (size_t)b * SEQL + col0);
                s[nt][0] = fmaf(s[nt][0], SCL, amv.x);
                s[nt][1] = fmaf(s[nt][1], SCL, amv.y);
                s[nt][2] = fmaf(s[nt][2], SCL, amv.x);
                s[nt][3] = fmaf(s[nt][3], SCL, amv.y);
            }
        } else {
            #pragma unroll
            for (int nt = 0; nt < 8; nt++) {
                int col0 = kt0 + nt * 8 + 2 * t;
                float2 amv = *(const float2*)(g_am + (size_t)b * SEQL + col0);
                s[nt][0] = (col0     - rq0     > WIN) ? -1e30f : fmaf(s[nt][0], SCL, amv.x);
                s[nt][1] = (col0 + 1 - rq0     > WIN) ? -1e30f : fmaf(s[nt][1], SCL, amv.y);
                s[nt][2] = (col0     - rq0 - 8 > WIN) ? -1e30f : fmaf(s[nt][2], SCL, amv.x);
                s[nt][3] = (col0 + 1 - rq0 - 8 > WIN) ? -1e30f : fmaf(s[nt][3], SCL, amv.y);
            }
        }

        float mx0 = -1e30f, mx1 = -1e30f;
        #pragma unroll
        for (int nt = 0; nt < 8; nt++) {
            mx0 = fmaxf(mx0, fmaxf(s[nt][0], s[nt][1]));
            mx1 = fmaxf(mx1, fmaxf(s[nt][2], s[nt][3]));
        }
        mx0 = fmaxf(mx0, __shfl_xor_sync(0xffffffffu, mx0, 1));
        mx0 = fmaxf(mx0, __shfl_xor_sync(0xffffffffu, mx0, 2));
        mx1 = fmaxf(mx1, __shfl_xor_sync(0xffffffffu, mx1, 1));
        mx1 = fmaxf(mx1, __shfl_xor_sync(0xffffffffu, mx1, 2));
        float mn0 = fmaxf(m0, mx0), mn1 = fmaxf(m1, mx1);
        float alpha0 = fexp2(m0 - mn0), alpha1 = fexp2(m1 - mn1);
        m0 = mn0; m1 = mn1;
        float ls0 = 0.f, ls1 = 0.f;
        #pragma unroll
        for (int nt = 0; nt < 8; nt++) {
            s[nt][0] = fexp2(s[nt][0] - mn0);
            s[nt][1] = fexp2(s[nt][1] - mn0);
            s[nt][2] = fexp2(s[nt][2] - mn1);
            s[nt][3] = fexp2(s[nt][3] - mn1);
            ls0 += s[nt][0] + s[nt][1];
            ls1 += s[nt][2] + s[nt][3];
        }
        ls0 += __shfl_xor_sync(0xffffffffu, ls0, 1);
        ls0 += __shfl_xor_sync(0xffffffffu, ls0, 2);
        ls1 += __shfl_xor_sync(0xffffffffu, ls1, 1);
        ls1 += __shfl_xor_sync(0xffffffffu, ls1, 2);
        l0 = l0 * alpha0 + ls0;
        l1 = l1 * alpha1 + ls1;
        #pragma unroll
        for (int dt = 0; dt < 8; dt++) {
            o[dt][0] *= alpha0; o[dt][1] *= alpha0;
            o[dt][2] *= alpha1; o[dt][3] *= alpha1;
        }

        #pragma unroll
        for (int kp = 0; kp < 4; kp++) {
            unsigned pah[4];
            pah[0] = pack_h2(s[2 * kp][0],     s[2 * kp][1]);
            pah[1] = pack_h2(s[2 * kp][2],     s[2 * kp][3]);
            pah[2] = pack_h2(s[2 * kp + 1][0], s[2 * kp + 1][1]);
            pah[3] = pack_h2(s[2 * kp + 1][2], s[2 * kp + 1][3]);
            #pragma unroll
            for (int dtp = 0; dtp < 4; dtp++) {
                unsigned vh[4];
                LDSM_X4_T(vh, VH + (kp * 16 * AP + dtp * 16) * 2 + loffV);
                mma_f16(o[2 * dtp], pah, &vh[0]);
                mma_f16(o[2 * dtp + 1], pah, &vh[2]);
            }
        }
        __syncthreads();
    }

    float inv0 = 1.f / l0, inv1 = 1.f / l1;
    const size_t ob = (size_t)(b * SEQL + rq0) * HIDDEN + h * HD + 2 * t;
    #pragma unroll
    for (int dt = 0; dt < 8; dt++) {
        int dc = dt * 8;
        *(unsigned*)(g_o16 + ob + dc) = pack_h2(o[dt][0] * inv0, o[dt][1] * inv0);
        *(unsigned*)(g_o16 + ob + 8 * HIDDEN + dc) = pack_h2(o[dt][2] * inv1, o[dt][3] * inv1);
    }
}

extern "C" void kernel_launch(void* const* d_in, const int* in_sizes, int n_in,
                              void* d_out, int out_size) {
    const float* hs = (const float*)d_in[0];
    const float* am = (const float*)d_in[1];
    const float* Wq = (const float*)d_in[2];
    const float* bq = (const float*)d_in[3];
    const float* Wk = (const float*)d_in[4];
    const float* bk = (const float*)d_in[5];
    const float* Wv = (const float*)d_in[6];
    const float* bv = (const float*)d_in[7];
    const float* Wo = (const float*)d_in[8];
    float* out = (float*)d_out;

    float* biasp;
    __half *ha, *wh, *wl, *o16;
    cudaGetSymbolAddress((void**)&biasp, g_bias);
    cudaGetSymbolAddress((void**)&ha,  g_ha);
    cudaGetSymbolAddress((void**)&wh,  g_w16h);
    cudaGetSymbolAddress((void**)&wl,  g_w16l);
    cudaGetSymbolAddress((void**)&o16, g_o16);

    cudaFuncSetAttribute(hgemm_kernel<0>, cudaFuncAttributeMaxDynamicSharedMemorySize, GEMM_SMEM);
    cudaFuncSetAttribute(hgemm_kernel<1>, cudaFuncAttributeMaxDynamicSharedMemorySize, GEMM_SMEM);
    cudaFuncSetAttribute(attn_kernel, cudaFuncAttributeMaxDynamicSharedMemorySize, ATTN_SMEM);

    split_all_kernel<<<(SPL_AM + 255) / 256, 256>>>(hs, Wq, Wk, Wv, Wo, bq, bk, bv, am);

    // QKV projection with fused bias + rope + fp16 split epilogue
    hgemm_kernel<1><<<dim3(QKVN / 128, MTOT / 128), 256, GEMM_SMEM>>>(
        ha, wh, wl, biasp, nullptr, QKVN);

    attn_kernel<<<dim3(SEQL / 64, BSZ * NH), 128, ATTN_SMEM>>>();

    hgemm_kernel<0><<<dim3(HIDDEN / 128, MTOT / 128), 256, GEMM_SMEM>>>(
        o16, wh + WO_OFF, wl + WO_OFF, nullptr, out, HIDDEN);
}

// round 15
// speedup vs baseline: 1.1884x; 1.1714x over previous
#include <cuda_runtime.h>
#include <cuda_bf16.h>
#include <cuda_fp16.h>
#include <math.h>
#include <stdint.h>

#define HIDDEN 1024
#define NH 16
#define NKV 4
#define HD 64
#define SEQL 2048
#define BSZ 2
#define KVD (NKV*HD)            /* 256  */
#define QKVN (HIDDEN + 2*KVD)   /* 1536 */
#define MTOT (BSZ*SEQL)         /* 4096 */
#define WIN 1534
#define LOG2E 1.44269504088896340736f

#define WQ_OFF 0
#define WK_OFF (1024*1024)
#define WV_OFF (1280*1024)
#define WO_OFF (1536*1024)
#define WTOT   (2560*1024)

__device__ __align__(16) __half  g_ha[(size_t)MTOT * HIDDEN];
__device__ __align__(16) __half  g_w16[(size_t)WTOT];
__device__ __align__(16) float   g_bias[QKVN];
__device__ __align__(16) __half  g_qh[(size_t)MTOT * HIDDEN];
__device__ __align__(16) __half  g_kh[(size_t)MTOT * KVD];
__device__ __align__(16) __half  g_vh[(size_t)MTOT * KVD];
__device__ __align__(16) __half  g_o16[(size_t)MTOT * HIDDEN];
__device__ __align__(16) float   g_am[BSZ * SEQL];
__device__ __align__(16) float2  g_sc[SEQL * 32];

// --------------------------- ptx helpers ----------------------------------
__device__ __forceinline__ void mma_f16(float* c, const unsigned* a, const unsigned* b) {
    asm volatile(
        "mma.sync.aligned.m16n8k16.row.col.f32.f16.f16.f32 "
        "{%0,%1,%2,%3}, {%4,%5,%6,%7}, {%8,%9}, {%0,%1,%2,%3};"
        : "+f"(c[0]), "+f"(c[1]), "+f"(c[2]), "+f"(c[3])
        : "r"(a[0]), "r"(a[1]), "r"(a[2]), "r"(a[3]), "r"(b[0]), "r"(b[1]));
}
#define LDSM_X4(R, ADDR) \
    asm volatile("ldmatrix.sync.aligned.m8n8.x4.shared.b16 {%0,%1,%2,%3}, [%4];" \
        : "=r"((R)[0]), "=r"((R)[1]), "=r"((R)[2]), "=r"((R)[3]) : "r"(ADDR))
#define LDSM_X4_T(R, ADDR) \
    asm volatile("ldmatrix.sync.aligned.m8n8.x4.trans.shared.b16 {%0,%1,%2,%3}, [%4];" \
        : "=r"((R)[0]), "=r"((R)[1]), "=r"((R)[2]), "=r"((R)[3]) : "r"(ADDR))
__device__ __forceinline__ void cp16(unsigned dst, const void* src) {
    asm volatile("cp.async.cg.shared.global [%0], [%1], 16;" :: "r"(dst), "l"(src) : "memory");
}
__device__ __forceinline__ void cp_commit() { asm volatile("cp.async.commit_group;" ::: "memory"); }
template<int N> __device__ __forceinline__ void cp_wait() {
    asm volatile("cp.async.wait_group %0;" :: "n"(N) : "memory");
}
__device__ __forceinline__ float fexp2(float x) {
    float y; asm("ex2.approx.f32 %0, %1;" : "=f"(y) : "f"(x)); return y;
}
__device__ __forceinline__ unsigned pack_h2(float x, float y) {
    __half2 h = __floats2half2_rn(x, y);
    return *reinterpret_cast<unsigned*>(&h);
}

#define SCL (0.125f * LOG2E)
#define AMS (-10000.0f * LOG2E)

// ----------------- convert inputs + sincos + bias + amask (one launch) ----
#define SPL_HS (MTOT*HIDDEN/4)
#define SPL_WQ (SPL_HS + HIDDEN*HIDDEN/4)
#define SPL_WK (SPL_WQ + KVD*HIDDEN/4)
#define SPL_WV (SPL_WK + KVD*HIDDEN/4)
#define SPL_WO (SPL_WV + HIDDEN*HIDDEN/4)
#define SPL_SC (SPL_WO + SEQL*32)
#define SPL_BI (SPL_SC + QKVN)
#define SPL_AM (SPL_BI + BSZ*SEQL)
__global__ void split_all_kernel(const float* __restrict__ hs,
                                 const float* __restrict__ Wq,
                                 const float* __restrict__ Wk,
                                 const float* __restrict__ Wv,
                                 const float* __restrict__ Wo,
                                 const float* __restrict__ bq,
                                 const float* __restrict__ bk,
                                 const float* __restrict__ bv,
                                 const float* __restrict__ amask) {
    int i = blockIdx.x * blockDim.x + threadIdx.x;
    if (i < SPL_WO) {
        const float* src; __half* dst; int off;
        if (i < SPL_HS)      { src = hs; dst = g_ha;           off = i; }
        else if (i < SPL_WQ) { src = Wq; dst = g_w16 + WQ_OFF; off = i - SPL_HS; }
        else if (i < SPL_WK) { src = Wk; dst = g_w16 + WK_OFF; off = i - SPL_WQ; }
        else if (i < SPL_WV) { src = Wv; dst = g_w16 + WV_OFF; off = i - SPL_WK; }
        else                 { src = Wo; dst = g_w16 + WO_OFF; off = i - SPL_WV; }
        float4 v = ((const float4*)src)[off];
        uint2 p;
        p.x = pack_h2(v.x, v.y);
        p.y = pack_h2(v.z, v.w);
        ((uint2*)dst)[off] = p;
        return;
    }
    if (i < SPL_SC) {
        int idx = i - SPL_WO;
        int s = idx >> 5, j = idx & 31;
        double invf = exp(-(double)j * 0.28782313662425572);
        double ang  = (double)s * invf;
        g_sc[idx] = make_float2((float)sin(ang), (float)cos(ang));
        return;
    }
    if (i < SPL_BI) {
        int idx = i - SPL_SC;
        g_bias[idx] = (idx < HIDDEN) ? bq[idx]
                     : (idx < HIDDEN + KVD ? bk[idx - HIDDEN] : bv[idx - HIDDEN - KVD]);
        return;
    }
    if (i < SPL_AM) {
        int idx = i - SPL_BI;
        g_am[idx] = amask[idx] * AMS;
    }
}

// ---------------------------------------------------------------------------
// fp16 single-precision-operand GEMM: C[m,n] = sum_k A[m,k]*B[n,k] (+bias)
// BM=BN=128, BK=32, 8 warps, 2 stages. 1 mma per (mt,n8) per k16.
// MODE 0: C fp32 (+bias)              [O-proj]
// MODE 1: fused epilogue — bias + rope(Q,K)/convert(V) -> fp16 globals.
// ---------------------------------------------------------------------------
#define GP 40
#define G_STG (2*128*GP)
#define EP 130                               /* fp32 staging row stride */
#define GEMM_SMEM (128*EP*4)                 /* 66560 > 2*G_STG*2=40960 */

template<int MODE>
__global__ __launch_bounds__(256) void hgemm_kernel(
    const __half* __restrict__ A, const __half* __restrict__ B,
    const float* __restrict__ bias, float* __restrict__ C, int N)
{
    extern __shared__ __align__(16) __half smg[];
    const unsigned sb = (unsigned)__cvta_generic_to_shared(smg);
    const int K = HIDDEN;
    const int bm = blockIdx.y * 128;
    const int bn = blockIdx.x * 128;
    const int tid = threadIdx.x, wid = tid >> 5, lane = tid & 31;
    const int g = lane >> 2, t = lane & 3;
    const int ln7 = lane & 7, sel = lane >> 3;
    const int wm = (wid >> 2) * 64, wn = (wid & 3) * 32;
    const int loffA = (((sel & 1) * 8 + ln7) * GP + (sel >> 1) * 8) * 2;
    const int loffB = (((sel >> 1) * 8 + ln7) * GP + (sel & 1) * 8) * 2;

    const __half* srcs[2] = {A + (size_t)bm * K, B + (size_t)bn * K};

    float acc[4][4][4];
    #pragma unroll
    for (int i = 0; i < 4; i++)
        #pragma unroll
        for (int j = 0; j < 4; j++)
            #pragma unroll
            for (int c = 0; c < 4; c++) acc[i][j][c] = 0.f;

    auto issue = [&](int k0, int stg) {
        #pragma unroll
        for (int l = 0; l < 4; l++) {
            int arr = l >> 1;
            int q = tid + (l & 1) * 256;
            int row = q >> 2, ch = q & 3;
            const __half* s = srcs[arr] + (size_t)row * K + k0 + ch * 8;
            unsigned d = sb + (stg * G_STG + arr * 128 * GP + row * GP + ch * 8) * 2;
            cp16(d, s);
        }
    };

    issue(0, 0); cp_commit();
    const int NTK = K / 32;
    for (int kt = 0; kt < NTK; kt++) {
        if (kt + 1 < NTK) issue((kt + 1) * 32, (kt + 1) & 1);
        cp_commit();
        cp_wait<1>();
        __syncthreads();
        const unsigned base = sb + ((kt & 1) * G_STG) * 2;
        #pragma unroll
        for (int ks = 0; ks < 32; ks += 16) {
            unsigned a4[4][4];
            #pragma unroll
            for (int mt = 0; mt < 4; mt++)
                LDSM_X4(a4[mt], base + ((wm + mt * 16) * GP + ks) * 2 + loffA);
            #pragma unroll
            for (int ntp = 0; ntp < 2; ntp++) {
                unsigned b4[4];
                LDSM_X4(b4, base + (128 * GP + (wn + ntp * 16) * GP + ks) * 2 + loffB);
                #pragma unroll
                for (int mt = 0; mt < 4; mt++) {
                    mma_f16(acc[mt][2 * ntp], a4[mt], &b4[0]);
                    mma_f16(acc[mt][2 * ntp + 1], a4[mt], &b4[2]);
                }
            }
        }
        __syncthreads();
    }

    if (MODE == 0) {
        #pragma unroll
        for (int mt = 0; mt < 4; mt++)
            #pragma unroll
            for (int nt = 0; nt < 4; nt++) {
                int r = bm + wm + mt * 16 + g;
                int ccol = wn + nt * 8 + 2 * t;
                float b0v = 0.f, b1v = 0.f;
                if (bias) { b0v = bias[bn + ccol]; b1v = bias[bn + ccol + 1]; }
                *(float2*)(C + (size_t)r * N + bn + ccol) =
                    make_float2(acc[mt][nt][0] + b0v, acc[mt][nt][1] + b1v);
                *(float2*)(C + (size_t)(r + 8) * N + bn + ccol) =
                    make_float2(acc[mt][nt][2] + b0v, acc[mt][nt][3] + b1v);
            }
        return;
    }

    // ---- MODE 1: stage fp32 tile (+bias) in smem, then rope/convert ----
    float* st = (float*)smg;
    #pragma unroll
    for (int mt = 0; mt < 4; mt++)
        #pragma unroll
        for (int nt = 0; nt < 4; nt++) {
            int r = wm + mt * 16 + g;
            int ccol = wn + nt * 8 + 2 * t;
            float b0v = bias[bn + ccol], b1v = bias[bn + ccol + 1];
            *(float2*)&st[r * EP + ccol] =
                make_float2(acc[mt][nt][0] + b0v, acc[mt][nt][1] + b1v);
            *(float2*)&st[(r + 8) * EP + ccol] =
                make_float2(acc[mt][nt][2] + b0v, acc[mt][nt][3] + b1v);
        }
    __syncthreads();

    if (bn < HIDDEN + KVD) {
        // Q (bn<1024) or K (1024<=bn<1280): rope then fp16
        __half* dst   = (bn < HIDDEN) ? g_qh : g_kh;
        const int str = (bn < HIDDEN) ? HIDDEN : KVD;
        const int noff = (bn < HIDDEN) ? bn : bn - HIDDEN;
        #pragma unroll
        for (int l = 0; l < 32; l++) {
            int idx = tid + l * 256;
            int row = idx >> 6;            // 0..127
            int p   = idx & 63;            // head(1b) x j(5b)
            int head = p >> 5, j = p & 31;
            int cl = head * 64 + j;
            float xr = st[row * EP + cl];
            float xp = st[row * EP + cl + 32];
            int m = bm + row;
            float2 sc = g_sc[(((m & (SEQL - 1))) << 5) | j];
            size_t o = (size_t)m * str + noff + cl;
            dst[o]      = __float2half_rn(xr * sc.y - xp * sc.x);
            dst[o + 32] = __float2half_rn(xr * sc.x + xp * sc.y);
        }
    } else {
        // V: straight fp16 convert
        const int noff = bn - HIDDEN - KVD;
        #pragma unroll
        for (int l = 0; l < 32; l++) {
            int idx = tid + l * 256;
            int row = idx >> 6;
            int c2  = (idx & 63) * 2;
            float x = st[row * EP + c2];
            float y = st[row * EP + c2 + 1];
            int m = bm + row;
            *(unsigned*)(g_vh + (size_t)m * KVD + noff + c2) = pack_h2(x, y);
        }
    }
}

// ---------------------------------------------------------------------------
// Flash attention (R10-proven): single fp16 K/V, Br=Bc=64, 4 warps,
// 2 smem arrays/stage, 2-stage cp.async, exp2 softmax, fp16 P+output.
// ---------------------------------------------------------------------------
#define AP 72
#define A_ARR (64*AP)
#define A_STG (2*A_ARR)
#define ATTN_SMEM (2*A_STG*2)      /* 36864 B */

__global__ __launch_bounds__(128) void attn_kernel()
{
    extern __shared__ __align__(16) __half sma[];
    const unsigned sb = (unsigned)__cvta_generic_to_shared(sma);

    const int qt0 = blockIdx.x * 64;
    const int b   = blockIdx.y >> 4;
    const int h   = blockIdx.y & 15;
    const int kvh = h >> 2;
    const int tid = threadIdx.x, wid = tid >> 5, lane = tid & 31;
    const int g = lane >> 2, t = lane & 3;
    const int ln7 = lane & 7, sel = lane >> 3;
    const int loffK = (((sel >> 1) * 8 + ln7) * AP + (sel & 1) * 8) * 2;
    const int loffV = (((sel & 1) * 8 + ln7) * AP + (sel >> 1) * 8) * 2;
    const int rq0 = qt0 + wid * 16 + g;

    unsigned Qah[4][4];
    {
        const size_t rb = (size_t)(b * SEQL + rq0) * HIDDEN + h * HD + 2 * t;
        #pragma unroll
        for (int ks = 0; ks < 4; ks++) {
            int d = ks * 16;
            Qah[ks][0] = *(const unsigned*)(g_qh + rb + d);
            Qah[ks][1] = *(const unsigned*)(g_qh + rb + 8 * HIDDEN + d);
            Qah[ks][2] = *(const unsigned*)(g_qh + rb + d + 8);
            Qah[ks][3] = *(const unsigned*)(g_qh + rb + 8 * HIDDEN + d + 8);
        }
    }

    const size_t kvbase = (size_t)(b * SEQL) * KVD + kvh * HD;
    const __half* srcs[2] = {g_kh + kvbase, g_vh + kvbase};

    auto issue = [&](int kt0, int stg) {
        #pragma unroll
        for (int l = 0; l < 8; l++) {
            int arr = l >> 2;
            int q = tid + (l & 3) * 128;
            int row = q >> 3, ch = q & 7;
            const __half* s = srcs[arr] + (size_t)(kt0 + row) * KVD + ch * 8;
            unsigned d = sb + (stg * A_STG + arr * A_ARR + row * AP + ch * 8) * 2;
            cp16(d, s);
        }
    };

    float o[8][4];
    #pragma unroll
    for (int dt = 0; dt < 8; dt++)
        #pragma unroll
        for (int c = 0; c < 4; c++) o[dt][c] = 0.f;
    float m0 = -1e30f, m1 = -1e30f, l0 = 0.f, l1 = 0.f;

    const int ktmax = min(SEQL, qt0 + 63 + WIN + 1);
    const int NT = (ktmax + 63) >> 6;

    issue(0, 0); cp_commit();
    for (int ti = 0; ti < NT; ti++) {
        const int kt0 = ti * 64;
        if (ti + 1 < NT) issue((ti + 1) * 64, (ti + 1) & 1);
        cp_commit();
        cp_wait<1>();
        __syncthreads();
        const unsigned base = sb + ((ti & 1) * A_STG) * 2;
        const unsigned KH = base, VH = base + A_ARR * 2;

        float s[8][4];
        #pragma unroll
        for (int nt = 0; nt < 8; nt++)
            #pragma unroll
            for (int c = 0; c < 4; c++) s[nt][c] = 0.f;

        #pragma unroll
        for (int ks = 0; ks < 4; ks++) {
            #pragma unroll
            for (int ntp = 0; ntp < 4; ntp++) {
                unsigned kh[4];
                LDSM_X4(kh, KH + (ntp * 16 * AP + ks * 16) * 2 + loffK);
                mma_f16(s[2 * ntp], Qah[ks], &kh[0]);
                mma_f16(s[2 * ntp + 1], Qah[ks], &kh[2]);
            }
        }

        if (kt0 + 63 - qt0 - wid * 16 <= WIN) {
            #pragma unroll
            for (int nt = 0; nt < 8; nt++) {
                int col0 = kt0 + nt * 8 + 2 * t;
                float2 amv = *(const float2*)(g_am + (size_t)b * SEQL + col0);
                s[nt][0] = fmaf(s[nt][0], SCL, amv.x);
                s[nt][1] = fmaf(s[nt][1], SCL, amv.y);
                s[nt][2] = fmaf(s[nt][2], SCL, amv.x);
                s[nt][3] = fmaf(s[nt][3], SCL, amv.y);
            }
        } else {
            #pragma unroll
            for (int nt = 0; nt < 8; nt++) {
                int col0 = kt0 + nt * 8 + 2 * t;
                float2 amv = *(const float2*)(g_am + (size_t)b * SEQL + col0);
                s[nt][0] = (col0     - rq0     > WIN) ? -1e30f : fmaf(s[nt][0], SCL, amv.x);
                s[nt][1] = (col0 + 1 - rq0     > WIN) ? -1e30f : fmaf(s[nt][1], SCL, amv.y);
                s[nt][2] = (col0     - rq0 - 8 > WIN) ? -1e30f : fmaf(s[nt][2], SCL, amv.x);
                s[nt][3] = (col0 + 1 - rq0 - 8 > WIN) ? -1e30f : fmaf(s[nt][3], SCL, amv.y);
            }
        }

        float mx0 = -1e30f, mx1 = -1e30f;
        #pragma unroll
        for (int nt = 0; nt < 8; nt++) {
            mx0 = fmaxf(mx0, fmaxf(s[nt][0], s[nt][1]));
            mx1 = fmaxf(mx1, fmaxf(s[nt][2], s[nt][3]));
        }
        mx0 = fmaxf(mx0, __shfl_xor_sync(0xffffffffu, mx0, 1));
        mx0 = fmaxf(mx0, __shfl_xor_sync(0xffffffffu, mx0, 2));
        mx1 = fmaxf(mx1, __shfl_xor_sync(0xffffffffu, mx1, 1));
        mx1 = fmaxf(mx1, __shfl_xor_sync(0xffffffffu, mx1, 2));
        float mn0 = fmaxf(m0, mx0), mn1 = fmaxf(m1, mx1);
        float alpha0 = fexp2(m0 - mn0), alpha1 = fexp2(m1 - mn1);
        m0 = mn0; m1 = mn1;
        float ls0 = 0.f, ls1 = 0.f;
        #pragma unroll
        for (int nt = 0; nt < 8; nt++) {
            s[nt][0] = fexp2(s[nt][0] - mn0);
            s[nt][1] = fexp2(s[nt][1] - mn0);
            s[nt][2] = fexp2(s[nt][2] - mn1);
            s[nt][3] = fexp2(s[nt][3] - mn1);
            ls0 += s[nt][0] + s[nt][1];
            ls1 += s[nt][2] + s[nt][3];
        }
        ls0 += __shfl_xor_sync(0xffffffffu, ls0, 1);
        ls0 += __shfl_xor_sync(0xffffffffu, ls0, 2);
        ls1 += __shfl_xor_sync(0xffffffffu, ls1, 1);
        ls1 += __shfl_xor_sync(0xffffffffu, ls1, 2);
        l0 = l0 * alpha0 + ls0;
        l1 = l1 * alpha1 + ls1;
        #pragma unroll
        for (int dt = 0; dt < 8; dt++) {
            o[dt][0] *= alpha0; o[dt][1] *= alpha0;
            o[dt][2] *= alpha1; o[dt][3] *= alpha1;
        }

        #pragma unroll
        for (int kp = 0; kp < 4; kp++) {
            unsigned pah[4];
            pah[0] = pack_h2(s[2 * kp][0],     s[2 * kp][1]);
            pah[1] = pack_h2(s[2 * kp][2],     s[2 * kp][3]);
            pah[2] = pack_h2(s[2 * kp + 1][0], s[2 * kp + 1][1]);
            pah[3] = pack_h2(s[2 * kp + 1][2], s[2 * kp + 1][3]);
            #pragma unroll
            for (int dtp = 0; dtp < 4; dtp++) {
                unsigned vh[4];
                LDSM_X4_T(vh, VH + (kp * 16 * AP + dtp * 16) * 2 + loffV);
                mma_f16(o[2 * dtp], pah, &vh[0]);
                mma_f16(o[2 * dtp + 1], pah, &vh[2]);
            }
        }
        __syncthreads();
    }

    float inv0 = 1.f / l0, inv1 = 1.f / l1;
    const size_t ob = (size_t)(b * SEQL + rq0) * HIDDEN + h * HD + 2 * t;
    #pragma unroll
    for (int dt = 0; dt < 8; dt++) {
        int dc = dt * 8;
        *(unsigned*)(g_o16 + ob + dc) = pack_h2(o[dt][0] * inv0, o[dt][1] * inv0);
        *(unsigned*)(g_o16 + ob + 8 * HIDDEN + dc) = pack_h2(o[dt][2] * inv1, o[dt][3] * inv1);
    }
}

extern "C" void kernel_launch(void* const* d_in, const int* in_sizes, int n_in,
                              void* d_out, int out_size) {
    const float* hs = (const float*)d_in[0];
    const float* am = (const float*)d_in[1];
    const float* Wq = (const float*)d_in[2];
    const float* bq = (const float*)d_in[3];
    const float* Wk = (const float*)d_in[4];
    const float* bk = (const float*)d_in[5];
    const float* Wv = (const float*)d_in[6];
    const float* bv = (const float*)d_in[7];
    const float* Wo = (const float*)d_in[8];
    float* out = (float*)d_out;

    float* biasp;
    __half *ha, *w16, *o16;
    cudaGetSymbolAddress((void**)&biasp, g_bias);
    cudaGetSymbolAddress((void**)&ha,  g_ha);
    cudaGetSymbolAddress((void**)&w16, g_w16);
    cudaGetSymbolAddress((void**)&o16, g_o16);

    cudaFuncSetAttribute(hgemm_kernel<0>, cudaFuncAttributeMaxDynamicSharedMemorySize, GEMM_SMEM);
    cudaFuncSetAttribute(hgemm_kernel<1>, cudaFuncAttributeMaxDynamicSharedMemorySize, GEMM_SMEM);
    cudaFuncSetAttribute(attn_kernel, cudaFuncAttributeMaxDynamicSharedMemorySize, ATTN_SMEM);

    split_all_kernel<<<(SPL_AM + 255) / 256, 256>>>(hs, Wq, Wk, Wv, Wo, bq, bk, bv, am);

    // QKV projection with fused bias + rope + fp16 convert epilogue
    hgemm_kernel<1><<<dim3(QKVN / 128, MTOT / 128), 256, GEMM_SMEM>>>(
        ha, w16, biasp, nullptr, QKVN);

    attn_kernel<<<dim3(SEQL / 64, BSZ * NH), 128, ATTN_SMEM>>>();

    hgemm_kernel<0><<<dim3(HIDDEN / 128, MTOT / 128), 256, GEMM_SMEM>>>(
        o16, w16 + WO_OFF, nullptr, out, HIDDEN);
}

// round 17
// speedup vs baseline: 1.2164x; 1.0235x over previous
#include <cuda_runtime.h>
#include <cuda_bf16.h>
#include <cuda_fp16.h>
#include <math.h>
#include <stdint.h>

#define HIDDEN 1024
#define NH 16
#define NKV 4
#define HD 64
#define SEQL 2048
#define BSZ 2
#define KVD (NKV*HD)            /* 256  */
#define QKVN (HIDDEN + 2*KVD)   /* 1536 */
#define MTOT (BSZ*SEQL)         /* 4096 */
#define WIN 1534
#define LOG2E 1.44269504088896340736f

#define WQ_OFF 0
#define WK_OFF (1024*1024)
#define WV_OFF (1280*1024)
#define WO_OFF (1536*1024)
#define WTOT   (2560*1024)

__device__ __align__(16) __half  g_ha[(size_t)MTOT * HIDDEN];
__device__ __align__(16) __half  g_w16[(size_t)WTOT];
__device__ __align__(16) float   g_bias[QKVN];
__device__ __align__(16) __half  g_qh[(size_t)MTOT * HIDDEN];
__device__ __align__(16) __half  g_kh[(size_t)MTOT * KVD];
__device__ __align__(16) __half  g_vh[(size_t)MTOT * KVD];
__device__ __align__(16) __half  g_o16[(size_t)MTOT * HIDDEN];
__device__ __align__(16) float   g_am[BSZ * SEQL];
__device__ __align__(16) float2  g_sc[SEQL * 32];

// --------------------------- ptx helpers ----------------------------------
__device__ __forceinline__ void mma_f16(float* c, const unsigned* a, const unsigned* b) {
    asm volatile(
        "mma.sync.aligned.m16n8k16.row.col.f32.f16.f16.f32 "
        "{%0,%1,%2,%3}, {%4,%5,%6,%7}, {%8,%9}, {%0,%1,%2,%3};"
        : "+f"(c[0]), "+f"(c[1]), "+f"(c[2]), "+f"(c[3])
        : "r"(a[0]), "r"(a[1]), "r"(a[2]), "r"(a[3]), "r"(b[0]), "r"(b[1]));
}
#define LDSM_X4(R, ADDR) \
    asm volatile("ldmatrix.sync.aligned.m8n8.x4.shared.b16 {%0,%1,%2,%3}, [%4];" \
        : "=r"((R)[0]), "=r"((R)[1]), "=r"((R)[2]), "=r"((R)[3]) : "r"(ADDR))
#define LDSM_X4_T(R, ADDR) \
    asm volatile("ldmatrix.sync.aligned.m8n8.x4.trans.shared.b16 {%0,%1,%2,%3}, [%4];" \
        : "=r"((R)[0]), "=r"((R)[1]), "=r"((R)[2]), "=r"((R)[3]) : "r"(ADDR))
__device__ __forceinline__ void cp16(unsigned dst, const void* src) {
    asm volatile("cp.async.cg.shared.global [%0], [%1], 16;" :: "r"(dst), "l"(src) : "memory");
}
__device__ __forceinline__ void cp_commit() { asm volatile("cp.async.commit_group;" ::: "memory"); }
template<int N> __device__ __forceinline__ void cp_wait() {
    asm volatile("cp.async.wait_group %0;" :: "n"(N) : "memory");
}
__device__ __forceinline__ float fexp2(float x) {
    float y; asm("ex2.approx.f32 %0, %1;" : "=f"(y) : "f"(x)); return y;
}
__device__ __forceinline__ unsigned pack_h2(float x, float y) {
    __half2 h = __floats2half2_rn(x, y);
    return *reinterpret_cast<unsigned*>(&h);
}

#define SCL (0.125f * LOG2E)
#define AMS (-10000.0f * LOG2E)

// ----------------- convert inputs + sincos + bias + amask (one launch) ----
#define SPL_HS (MTOT*HIDDEN/4)
#define SPL_WQ (SPL_HS + HIDDEN*HIDDEN/4)
#define SPL_WK (SPL_WQ + KVD*HIDDEN/4)
#define SPL_WV (SPL_WK + KVD*HIDDEN/4)
#define SPL_WO (SPL_WV + HIDDEN*HIDDEN/4)
#define SPL_SC (SPL_WO + SEQL*32)
#define SPL_BI (SPL_SC + QKVN)
#define SPL_AM (SPL_BI + BSZ*SEQL)
__global__ void split_all_kernel(const float* __restrict__ hs,
                                 const float* __restrict__ Wq,
                                 const float* __restrict__ Wk,
                                 const float* __restrict__ Wv,
                                 const float* __restrict__ Wo,
                                 const float* __restrict__ bq,
                                 const float* __restrict__ bk,
                                 const float* __restrict__ bv,
                                 const float* __restrict__ amask) {
    int i = blockIdx.x * blockDim.x + threadIdx.x;
    if (i < SPL_WO) {
        const float* src; __half* dst; int off;
        if (i < SPL_HS)      { src = hs; dst = g_ha;           off = i; }
        else if (i < SPL_WQ) { src = Wq; dst = g_w16 + WQ_OFF; off = i - SPL_HS; }
        else if (i < SPL_WK) { src = Wk; dst = g_w16 + WK_OFF; off = i - SPL_WQ; }
        else if (i < SPL_WV) { src = Wv; dst = g_w16 + WV_OFF; off = i - SPL_WK; }
        else                 { src = Wo; dst = g_w16 + WO_OFF; off = i - SPL_WV; }
        float4 v = ((const float4*)src)[off];
        uint2 p;
        p.x = pack_h2(v.x, v.y);
        p.y = pack_h2(v.z, v.w);
        ((uint2*)dst)[off] = p;
        return;
    }
    if (i < SPL_SC) {
        int idx = i - SPL_WO;
        int s = idx >> 5, j = idx & 31;
        double invf = exp(-(double)j * 0.28782313662425572);
        double ang  = (double)s * invf;
        g_sc[idx] = make_float2((float)sin(ang), (float)cos(ang));
        return;
    }
    if (i < SPL_BI) {
        int idx = i - SPL_SC;
        g_bias[idx] = (idx < HIDDEN) ? bq[idx]
                     : (idx < HIDDEN + KVD ? bk[idx - HIDDEN] : bv[idx - HIDDEN - KVD]);
        return;
    }
    if (i < SPL_AM) {
        int idx = i - SPL_BI;
        g_am[idx] = amask[idx] * AMS;
    }
}

// ---------------------------------------------------------------------------
// fp16 GEMM: C[m,n] = sum_k A[m,k]*B[n,k] (+bias). BM=BN=128, BK=32,
// 8 warps, 3-stage cp.async (one barrier per k-iter).
// MODE 0: C fp32 (+bias)              [O-proj]
// MODE 1: fused epilogue — bias + rope(Q,K)/convert(V) -> fp16 globals.
// ---------------------------------------------------------------------------
#define GP 40
#define G_STG (2*128*GP)
#define EP 130                               /* fp32 staging row stride */
#define GEMM_SMEM (128*EP*4)                 /* 66560 > 3*G_STG*2=61440 */

template<int MODE>
__global__ __launch_bounds__(256) void hgemm_kernel(
    const __half* __restrict__ A, const __half* __restrict__ B,
    const float* __restrict__ bias, float* __restrict__ C, int N)
{
    extern __shared__ __align__(16) __half smg[];
    const unsigned sb = (unsigned)__cvta_generic_to_shared(smg);
    const int K = HIDDEN;
    const int bm = blockIdx.y * 128;
    const int bn = blockIdx.x * 128;
    const int tid = threadIdx.x, wid = tid >> 5, lane = tid & 31;
    const int g = lane >> 2, t = lane & 3;
    const int ln7 = lane & 7, sel = lane >> 3;
    const int wm = (wid >> 2) * 64, wn = (wid & 3) * 32;
    const int loffA = (((sel & 1) * 8 + ln7) * GP + (sel >> 1) * 8) * 2;
    const int loffB = (((sel >> 1) * 8 + ln7) * GP + (sel & 1) * 8) * 2;

    const __half* srcs[2] = {A + (size_t)bm * K, B + (size_t)bn * K};

    float acc[4][4][4];
    #pragma unroll
    for (int i = 0; i < 4; i++)
        #pragma unroll
        for (int j = 0; j < 4; j++)
            #pragma unroll
            for (int c = 0; c < 4; c++) acc[i][j][c] = 0.f;

    auto issue = [&](int k0, int stg) {
        #pragma unroll
        for (int l = 0; l < 4; l++) {
            int arr = l >> 1;
            int q = tid + (l & 1) * 256;
            int row = q >> 2, ch = q & 3;
            const __half* s = srcs[arr] + (size_t)row * K + k0 + ch * 8;
            unsigned d = sb + (stg * G_STG + arr * 128 * GP + row * GP + ch * 8) * 2;
            cp16(d, s);
        }
    };

    const int NTK = K / 32;                  /* 32 */
    issue(0, 0); cp_commit();
    issue(32, 1); cp_commit();

    for (int kt = 0; kt < NTK; kt++) {
        if (kt + 1 < NTK) cp_wait<1>(); else cp_wait<0>();
        __syncthreads();
        if (kt + 2 < NTK) { issue((kt + 2) * 32, (kt + 2) % 3); cp_commit(); }

        const unsigned base = sb + ((kt % 3) * G_STG) * 2;
        #pragma unroll
        for (int ks = 0; ks < 32; ks += 16) {
            unsigned a4[4][4];
            #pragma unroll
            for (int mt = 0; mt < 4; mt++)
                LDSM_X4(a4[mt], base + ((wm + mt * 16) * GP + ks) * 2 + loffA);
            #pragma unroll
            for (int ntp = 0; ntp < 2; ntp++) {
                unsigned b4[4];
                LDSM_X4(b4, base + (128 * GP + (wn + ntp * 16) * GP + ks) * 2 + loffB);
                #pragma unroll
                for (int mt = 0; mt < 4; mt++) {
                    mma_f16(acc[mt][2 * ntp], a4[mt], &b4[0]);
                    mma_f16(acc[mt][2 * ntp + 1], a4[mt], &b4[2]);
                }
            }
        }
    }

    if (MODE == 0) {
        #pragma unroll
        for (int mt = 0; mt < 4; mt++)
            #pragma unroll
            for (int nt = 0; nt < 4; nt++) {
                int r = bm + wm + mt * 16 + g;
                int ccol = wn + nt * 8 + 2 * t;
                float b0v = 0.f, b1v = 0.f;
                if (bias) { b0v = bias[bn + ccol]; b1v = bias[bn + ccol + 1]; }
                *(float2*)(C + (size_t)r * N + bn + ccol) =
                    make_float2(acc[mt][nt][0] + b0v, acc[mt][nt][1] + b1v);
                *(float2*)(C + (size_t)(r + 8) * N + bn + ccol) =
                    make_float2(acc[mt][nt][2] + b0v, acc[mt][nt][3] + b1v);
            }
        return;
    }

    // ---- MODE 1: stage fp32 tile (+bias) in smem, then rope/convert ----
    __syncthreads();                 // all warps done reading pipeline smem
    float* st = (float*)smg;
    #pragma unroll
    for (int mt = 0; mt < 4; mt++)
        #pragma unroll
        for (int nt = 0; nt < 4; nt++) {
            int r = wm + mt * 16 + g;
            int ccol = wn + nt * 8 + 2 * t;
            float b0v = bias[bn + ccol], b1v = bias[bn + ccol + 1];
            *(float2*)&st[r * EP + ccol] =
                make_float2(acc[mt][nt][0] + b0v, acc[mt][nt][1] + b1v);
            *(float2*)&st[(r + 8) * EP + ccol] =
                make_float2(acc[mt][nt][2] + b0v, acc[mt][nt][3] + b1v);
        }
    __syncthreads();

    if (bn < HIDDEN + KVD) {
        // Q (bn<1024) or K (1024<=bn<1280): rope then fp16
        __half* dst   = (bn < HIDDEN) ? g_qh : g_kh;
        const int str = (bn < HIDDEN) ? HIDDEN : KVD;
        const int noff = (bn < HIDDEN) ? bn : bn - HIDDEN;
        #pragma unroll
        for (int l = 0; l < 32; l++) {
            int idx = tid + l * 256;
            int row = idx >> 6;            // 0..127
            int p   = idx & 63;            // head(1b) x j(5b)
            int head = p >> 5, j = p & 31;
            int cl = head * 64 + j;
            float xr = st[row * EP + cl];
            float xp = st[row * EP + cl + 32];
            int m = bm + row;
            float2 sc = g_sc[(((m & (SEQL - 1))) << 5) | j];
            size_t o = (size_t)m * str + noff + cl;
            dst[o]      = __float2half_rn(xr * sc.y - xp * sc.x);
            dst[o + 32] = __float2half_rn(xr * sc.x + xp * sc.y);
        }
    } else {
        // V: straight fp16 convert
        const int noff = bn - HIDDEN - KVD;
        #pragma unroll
        for (int l = 0; l < 32; l++) {
            int idx = tid + l * 256;
            int row = idx >> 6;
            int c2  = (idx & 63) * 2;
            float x = st[row * EP + c2];
            float y = st[row * EP + c2 + 1];
            int m = bm + row;
            *(unsigned*)(g_vh + (size_t)m * KVD + noff + c2) = pack_h2(x, y);
        }
    }
}

// ---------------------------------------------------------------------------
// Flash attention (R10-proven): single fp16 K/V, Br=Bc=64, 4 warps,
// 2 smem arrays/stage, 2-stage cp.async, exp2 softmax, fp16 P+output.
// ---------------------------------------------------------------------------
#define AP 72
#define A_ARR (64*AP)
#define A_STG (2*A_ARR)
#define ATTN_SMEM (2*A_STG*2)      /* 36864 B */

__global__ __launch_bounds__(128) void attn_kernel()
{
    extern __shared__ __align__(16) __half sma[];
    const unsigned sb = (unsigned)__cvta_generic_to_shared(sma);

    const int qt0 = blockIdx.x * 64;
    const int b   = blockIdx.y >> 4;
    const int h   = blockIdx.y & 15;
    const int kvh = h >> 2;
    const int tid = threadIdx.x, wid = tid >> 5, lane = tid & 31;
    const int g = lane >> 2, t = lane & 3;
    const int ln7 = lane & 7, sel = lane >> 3;
    const int loffK = (((sel >> 1) * 8 + ln7) * AP + (sel & 1) * 8) * 2;
    const int loffV = (((sel & 1) * 8 + ln7) * AP + (sel >> 1) * 8) * 2;
    const int rq0 = qt0 + wid * 16 + g;

    unsigned Qah[4][4];
    {
        const size_t rb = (size_t)(b * SEQL + rq0) * HIDDEN + h * HD + 2 * t;
        #pragma unroll
        for (int ks = 0; ks < 4; ks++) {
            int d = ks * 16;
            Qah[ks][0] = *(const unsigned*)(g_qh + rb + d);
            Qah[ks][1] = *(const unsigned*)(g_qh + rb + 8 * HIDDEN + d);
            Qah[ks][2] = *(const unsigned*)(g_qh + rb + d + 8);
            Qah[ks][3] = *(const unsigned*)(g_qh + rb + 8 * HIDDEN + d + 8);
        }
    }

    const size_t kvbase = (size_t)(b * SEQL) * KVD + kvh * HD;
    const __half* srcs[2] = {g_kh + kvbase, g_vh + kvbase};

    auto issue = [&](int kt0, int stg) {
        #pragma unroll
        for (int l = 0; l < 8; l++) {
            int arr = l >> 2;
            int q = tid + (l & 3) * 128;
            int row = q >> 3, ch = q & 7;
            const __half* s = srcs[arr] + (size_t)(kt0 + row) * KVD + ch * 8;
            unsigned d = sb + (stg * A_STG + arr * A_ARR + row * AP + ch * 8) * 2;
            cp16(d, s);
        }
    };

    float o[8][4];
    #pragma unroll
    for (int dt = 0; dt < 8; dt++)
        #pragma unroll
        for (int c = 0; c < 4; c++) o[dt][c] = 0.f;
    float m0 = -1e30f, m1 = -1e30f, l0 = 0.f, l1 = 0.f;

    const int ktmax = min(SEQL, qt0 + 63 + WIN + 1);
    const int NT = (ktmax + 63) >> 6;

    issue(0, 0); cp_commit();
    for (int ti = 0; ti < NT; ti++) {
        const int kt0 = ti * 64;
        if (ti + 1 < NT) issue((ti + 1) * 64, (ti + 1) & 1);
        cp_commit();
        cp_wait<1>();
        __syncthreads();
        const unsigned base = sb + ((ti & 1) * A_STG) * 2;
        const unsigned KH = base, VH = base + A_ARR * 2;

        float s[8][4];
        #pragma unroll
        for (int nt = 0; nt < 8; nt++)
            #pragma unroll
            for (int c = 0; c < 4; c++) s[nt][c] = 0.f;

        #pragma unroll
        for (int ks = 0; ks < 4; ks++) {
            #pragma unroll
            for (int ntp = 0; ntp < 4; ntp++) {
                unsigned kh[4];
                LDSM_X4(kh, KH + (ntp * 16 * AP + ks * 16) * 2 + loffK);
                mma_f16(s[2 * ntp], Qah[ks], &kh[0]);
                mma_f16(s[2 * ntp + 1], Qah[ks], &kh[2]);
            }
        }

        if (kt0 + 63 - qt0 - wid * 16 <= WIN) {
            #pragma unroll
            for (int nt = 0; nt < 8; nt++) {
                int col0 = kt0 + nt * 8 + 2 * t;
                float2 amv = *(const float2*)(g_am + (size_t)b * SEQL + col0);
                s[nt][0] = fmaf(s[nt][0], SCL, amv.x);
                s[nt][1] = fmaf(s[nt][1], SCL, amv.y);
                s[nt][2] = fmaf(s[nt][2], SCL, amv.x);
                s[nt][3] = fmaf(s[nt][3], SCL, amv.y);
            }
        } else {
            #pragma unroll
            for (int nt = 0; nt < 8; nt++) {
                int col0 = kt0 + nt * 8 + 2 * t;
                float2 amv = *(const float2*)(g_am + (size_t)b * SEQL + col0);
                s[nt][0] = (col0     - rq0     > WIN) ? -1e30f : fmaf(s[nt][0], SCL, amv.x);
                s[nt][1] = (col0 + 1 - rq0     > WIN) ? -1e30f : fmaf(s[nt][1], SCL, amv.y);
                s[nt][2] = (col0     - rq0 - 8 > WIN) ? -1e30f : fmaf(s[nt][2], SCL, amv.x);
                s[nt][3] = (col0 + 1 - rq0 - 8 > WIN) ? -1e30f : fmaf(s[nt][3], SCL, amv.y);
            }
        }

        float mx0 = -1e30f, mx1 = -1e30f;
        #pragma unroll
        for (int nt = 0; nt < 8; nt++) {
            mx0 = fmaxf(mx0, fmaxf(s[nt][0], s[nt][1]));
            mx1 = fmaxf(mx1, fmaxf(s[nt][2], s[nt][3]));
        }
        mx0 = fmaxf(mx0, __shfl_xor_sync(0xffffffffu, mx0, 1));
        mx0 = fmaxf(mx0, __shfl_xor_sync(0xffffffffu, mx0, 2));
        mx1 = fmaxf(mx1, __shfl_xor_sync(0xffffffffu, mx1, 1));
        mx1 = fmaxf(mx1, __shfl_xor_sync(0xffffffffu, mx1, 2));
        float mn0 = fmaxf(m0, mx0), mn1 = fmaxf(m1, mx1);
        float alpha0 = fexp2(m0 - mn0), alpha1 = fexp2(m1 - mn1);
        m0 = mn0; m1 = mn1;
        float ls0 = 0.f, ls1 = 0.f;
        #pragma unroll
        for (int nt = 0; nt < 8; nt++) {
            s[nt][0] = fexp2(s[nt][0] - mn0);
            s[nt][1] = fexp2(s[nt][1] - mn0);
            s[nt][2] = fexp2(s[nt][2] - mn1);
            s[nt][3] = fexp2(s[nt][3] - mn1);
            ls0 += s[nt][0] + s[nt][1];
            ls1 += s[nt][2] + s[nt][3];
        }
        ls0 += __shfl_xor_sync(0xffffffffu, ls0, 1);
        ls0 += __shfl_xor_sync(0xffffffffu, ls0, 2);
        ls1 += __shfl_xor_sync(0xffffffffu, ls1, 1);
        ls1 += __shfl_xor_sync(0xffffffffu, ls1, 2);
        l0 = l0 * alpha0 + ls0;
        l1 = l1 * alpha1 + ls1;
        #pragma unroll
        for (int dt = 0; dt < 8; dt++) {
            o[dt][0] *= alpha0; o[dt][1] *= alpha0;
            o[dt][2] *= alpha1; o[dt][3] *= alpha1;
        }

        #pragma unroll
        for (int kp = 0; kp < 4; kp++) {
            unsigned pah[4];
            pah[0] = pack_h2(s[2 * kp][0],     s[2 * kp][1]);
            pah[1] = pack_h2(s[2 * kp][2],     s[2 * kp][3]);
            pah[2] = pack_h2(s[2 * kp + 1][0], s[2 * kp + 1][1]);
            pah[3] = pack_h2(s[2 * kp + 1][2], s[2 * kp + 1][3]);
            #pragma unroll
            for (int dtp = 0; dtp < 4; dtp++) {
                unsigned vh[4];
                LDSM_X4_T(vh, VH + (kp * 16 * AP + dtp * 16) * 2 + loffV);
                mma_f16(o[2 * dtp], pah, &vh[0]);
                mma_f16(o[2 * dtp + 1], pah, &vh[2]);
            }
        }
        __syncthreads();
    }

    float inv0 = 1.f / l0, inv1 = 1.f / l1;
    const size_t ob = (size_t)(b * SEQL + rq0) * HIDDEN + h * HD + 2 * t;
    #pragma unroll
    for (int dt = 0; dt < 8; dt++) {
        int dc = dt * 8;
        *(unsigned*)(g_o16 + ob + dc) = pack_h2(o[dt][0] * inv0, o[dt][1] * inv0);
        *(unsigned*)(g_o16 + ob + 8 * HIDDEN + dc) = pack_h2(o[dt][2] * inv1, o[dt][3] * inv1);
    }
}

extern "C" void kernel_launch(void* const* d_in, const int* in_sizes, int n_in,
                              void* d_out, int out_size) {
    const float* hs = (const float*)d_in[0];
    const float* am = (const float*)d_in[1];
    const float* Wq = (const float*)d_in[2];
    const float* bq = (const float*)d_in[3];
    const float* Wk = (const float*)d_in[4];
    const float* bk = (const float*)d_in[5];
    const float* Wv = (const float*)d_in[6];
    const float* bv = (const float*)d_in[7];
    const float* Wo = (const float*)d_in[8];
    float* out = (float*)d_out;

    float* biasp;
    __half *ha, *w16, *o16;
    cudaGetSymbolAddress((void**)&biasp, g_bias);
    cudaGetSymbolAddress((void**)&ha,  g_ha);
    cudaGetSymbolAddress((void**)&w16, g_w16);
    cudaGetSymbolAddress((void**)&o16, g_o16);

    cudaFuncSetAttribute(hgemm_kernel<0>, cudaFuncAttributeMaxDynamicSharedMemorySize, GEMM_SMEM);
    cudaFuncSetAttribute(hgemm_kernel<1>, cudaFuncAttributeMaxDynamicSharedMemorySize, GEMM_SMEM);
    cudaFuncSetAttribute(attn_kernel, cudaFuncAttributeMaxDynamicSharedMemorySize, ATTN_SMEM);

    split_all_kernel<<<(SPL_AM + 255) / 256, 256>>>(hs, Wq, Wk, Wv, Wo, bq, bk, bv, am);

    // QKV projection with fused bias + rope + fp16 convert epilogue
    hgemm_kernel<1><<<dim3(QKVN / 128, MTOT / 128), 256, GEMM_SMEM>>>(
        ha, w16, biasp, nullptr, QKVN);

    attn_kernel<<<dim3(SEQL / 64, BSZ * NH), 128, ATTN_SMEM>>>();

    hgemm_kernel<0><<<dim3(HIDDEN / 128, MTOT / 128), 256, GEMM_SMEM>>>(
        o16, w16 + WO_OFF, nullptr, out, HIDDEN);
}